// round 7
// baseline (speedup 1.0000x reference)
#include <cuda_runtime.h>
#include <math.h>
#include <stdint.h>

// Problem constants
#define DIMX   2048
#define HEADS  16
#define HD     128
#define BATCH  4
#define SEQ    2048
#define M_TOT  8192
#define N_TOT  8192
#define K_TOT  2048

// Scan chunking
#define NCHUNK 32
#define CLEN   (SEQ / NCHUNK)
#define NCH    (BATCH * HEADS * HD)

// Scratch
__device__ float g_combined[(size_t)M_TOT * N_TOT];
__device__ float g_chunkmax[(size_t)NCHUNK * NCH];
__device__ float g_Ar[(size_t)M_TOT * K_TOT];
__device__ float g_Br[(size_t)N_TOT * K_TOT];

// ---------------------------------------------------------------------------
// PTX helpers
// ---------------------------------------------------------------------------
__device__ __forceinline__ uint32_t smem_u32(const void* p) {
    uint32_t a;
    asm("{ .reg .u64 t; cvta.to.shared.u64 t, %1; cvt.u32.u64 %0, t; }" : "=r"(a) : "l"(p));
    return a;
}
__device__ __forceinline__ uint32_t f2tf32(float f) {
    uint32_t o; asm("cvt.rna.tf32.f32 %0, %1;" : "=r"(o) : "f"(f)); return o;
}
__device__ __forceinline__ void cp_async16(uint32_t dst, const void* src) {
    asm volatile("cp.async.cg.shared.global [%0], [%1], 16;\n" :: "r"(dst), "l"(src));
}
__device__ __forceinline__ void cp_commit() { asm volatile("cp.async.commit_group;\n"); }
template <int N> __device__ __forceinline__ void cp_wait() {
    asm volatile("cp.async.wait_group %0;\n" :: "n"(N));
}
__device__ __forceinline__ void ldmat_x4(uint32_t& r0, uint32_t& r1, uint32_t& r2, uint32_t& r3,
                                         uint32_t addr) {
    asm volatile("ldmatrix.sync.aligned.m8n8.x4.shared.b16 {%0,%1,%2,%3}, [%4];"
                 : "=r"(r0), "=r"(r1), "=r"(r2), "=r"(r3) : "r"(addr));
}
__device__ __forceinline__ void mma_tf32(float& c0, float& c1, float& c2, float& c3,
                                         uint32_t a0, uint32_t a1, uint32_t a2, uint32_t a3,
                                         uint32_t b0, uint32_t b1) {
    asm volatile(
        "mma.sync.aligned.m16n8k8.row.col.f32.tf32.tf32.f32 "
        "{%0,%1,%2,%3}, {%4,%5,%6,%7}, {%8,%9}, {%0,%1,%2,%3};\n"
        : "+f"(c0), "+f"(c1), "+f"(c2), "+f"(c3)
        : "r"(a0), "r"(a1), "r"(a2), "r"(a3), "r"(b0), "r"(b1));
}
#define SWZ128(off) ((off) ^ (((off) >> 3) & 0x70))

// ---------------------------------------------------------------------------
// Kernel 0: round x and W to tf32 (rna)
// ---------------------------------------------------------------------------
__global__ void cvt_kernel(const float4* __restrict__ x, const float4* __restrict__ w) {
    const size_t N4 = (size_t)M_TOT * K_TOT / 4;
    size_t i = (size_t)blockIdx.x * blockDim.x + threadIdx.x;
    float4* Ao = (float4*)g_Ar;
    float4* Bo = (float4*)g_Br;
    if (i < N4) {
        float4 v = x[i];
        float4 o;
        o.x = __uint_as_float(f2tf32(v.x));
        o.y = __uint_as_float(f2tf32(v.y));
        o.z = __uint_as_float(f2tf32(v.z));
        o.w = __uint_as_float(f2tf32(v.w));
        Ao[i] = o;
    } else if (i < 2 * N4) {
        size_t j = i - N4;
        float4 v = w[j];
        float4 o;
        o.x = __uint_as_float(f2tf32(v.x));
        o.y = __uint_as_float(f2tf32(v.y));
        o.z = __uint_as_float(f2tf32(v.z));
        o.w = __uint_as_float(f2tf32(v.w));
        Bo[j] = o;
    }
}

// ---------------------------------------------------------------------------
// Kernel 1: TF32 mma.sync GEMM with ldmatrix fragment loads
// CTA tile 128x256, BK=32 (128B rows, SW128 swizzle), 8 warps (2x4), warp 64x64
// 4-stage cp.async ring, one __syncthreads per K-stage
// ---------------------------------------------------------------------------
#define BM 128
#define BN 256
#define BK 32
#define KT (K_TOT / BK)                        // 64
#define STAGES 4
#define A_STAGE_BYTES (BM * BK * 4)            // 16384
#define B_STAGE_BYTES (BN * BK * 4)            // 32768
#define STAGE_BYTES (A_STAGE_BYTES + B_STAGE_BYTES)
#define SMEM_DYN (STAGES * STAGE_BYTES + 1024) // 197632

__global__ __launch_bounds__(256, 1)
void gemm_tf32_kernel() {
    extern __shared__ char dynsmem[];

    const int tid  = threadIdx.x;
    const int warp = tid >> 5;
    const int lane = tid & 31;
    const int bm   = blockIdx.y * BM;
    const int bn   = blockIdx.x * BN;

    const uint32_t sbase = (smem_u32(dynsmem) + 1023u) & ~1023u;

    const int wm = (warp >> 2) * 64;   // warp m origin: 0 / 64
    const int wn = (warp & 3) * 64;    // warp n origin: 0..192

    // ldmatrix lane geometry
    const int lr   = lane & 7;           // row within 8-row tile; also swizzle key
    const int gA1  = (lane >> 3) & 1;    // A: +8 rows
    const int gA2  = lane >> 4;          // A: +1 k-chunk (16B)
    const int gB1  = lane >> 4;          // B: +8 rows
    const int gB2  = (lane >> 3) & 1;    // B: +1 k-chunk

    // Per-mf / per-nfp row-base byte offsets within a stage tile
    uint32_t aRow[4], bRow[4];
    #pragma unroll
    for (int mf = 0; mf < 4; mf++)
        aRow[mf] = (uint32_t)(wm + mf * 16 + gA1 * 8 + lr) * 128u;
    #pragma unroll
    for (int nfp = 0; nfp < 4; nfp++)
        bRow[nfp] = (uint32_t)(wn + nfp * 16 + gB1 * 8 + lr) * 128u;

    // cp.async slot precompute: A = 4 x 16B/thread/stage, B = 8 x 16B
    uint32_t swA[4]; uint32_t ofsA[4];   // element offsets into g_Ar (excl. k)
    #pragma unroll
    for (int i = 0; i < 4; i++) {
        int c = tid + i * 256;           // 0..1023
        int row = c >> 3, ch = c & 7;
        swA[i]  = SWZ128((uint32_t)(row * 128 + ch * 16));
        ofsA[i] = (uint32_t)((bm + row) * K_TOT + ch * 4);
    }
    uint32_t swB[8]; uint32_t ofsB[8];
    #pragma unroll
    for (int i = 0; i < 8; i++) {
        int c = tid + i * 256;           // 0..2047
        int row = c >> 3, ch = c & 7;
        swB[i]  = SWZ128((uint32_t)(row * 128 + ch * 16));
        ofsB[i] = (uint32_t)((bn + row) * K_TOT + ch * 4);
    }

    float acc[4][8][4];
    #pragma unroll
    for (int i = 0; i < 4; i++)
        #pragma unroll
        for (int j = 0; j < 8; j++)
            #pragma unroll
            for (int v = 0; v < 4; v++) acc[i][j][v] = 0.0f;

    auto load_stage = [&](int buf, int kt) {
        const uint32_t da = sbase + buf * STAGE_BYTES;
        const uint32_t db = da + A_STAGE_BYTES;
        const uint32_t ko = (uint32_t)(kt * BK);
        #pragma unroll
        for (int i = 0; i < 4; i++) cp_async16(da + swA[i], g_Ar + ofsA[i] + ko);
        #pragma unroll
        for (int i = 0; i < 8; i++) cp_async16(db + swB[i], g_Br + ofsB[i] + ko);
        cp_commit();
    };

    // Prologue: stages 0..2 (stage s lives in buffer s % 4)
    load_stage(0, 0);
    load_stage(1, 1);
    load_stage(2, 2);

    #pragma unroll 1
    for (int kt = 0; kt < KT; kt++) {
        if (kt < KT - 2)       cp_wait<2>();
        else if (kt == KT - 2) cp_wait<1>();
        else                   cp_wait<0>();
        __syncthreads();

        // Issue next stage's loads into the buffer freed last iteration
        if (kt + 3 < KT) load_stage((kt + 3) & 3, kt + 3);

        const uint32_t aOff = sbase + (kt & 3) * STAGE_BYTES;
        const uint32_t bOff = aOff + A_STAGE_BYTES;

        #pragma unroll
        for (int ks = 0; ks < 4; ks++) {       // 4 x K=8 substeps
            const int kc = ks * 2;             // 16B-chunk index of this k8
            uint32_t a[4][4];
            #pragma unroll
            for (int mf = 0; mf < 4; mf++) {
                uint32_t addr = aOff + aRow[mf] + ((uint32_t)((kc + gA2) ^ lr) << 4);
                ldmat_x4(a[mf][0], a[mf][1], a[mf][2], a[mf][3], addr);
            }
            uint32_t b[4][4];
            #pragma unroll
            for (int nfp = 0; nfp < 4; nfp++) {
                uint32_t addr = bOff + bRow[nfp] + ((uint32_t)((kc + gB2) ^ lr) << 4);
                ldmat_x4(b[nfp][0], b[nfp][1], b[nfp][2], b[nfp][3], addr);
            }
            #pragma unroll
            for (int mf = 0; mf < 4; mf++)
                #pragma unroll
                for (int nfp = 0; nfp < 4; nfp++) {
                    mma_tf32(acc[mf][2 * nfp][0], acc[mf][2 * nfp][1],
                             acc[mf][2 * nfp][2], acc[mf][2 * nfp][3],
                             a[mf][0], a[mf][1], a[mf][2], a[mf][3],
                             b[nfp][0], b[nfp][1]);
                    mma_tf32(acc[mf][2 * nfp + 1][0], acc[mf][2 * nfp + 1][1],
                             acc[mf][2 * nfp + 1][2], acc[mf][2 * nfp + 1][3],
                             a[mf][0], a[mf][1], a[mf][2], a[mf][3],
                             b[nfp][2], b[nfp][3]);
                }
        }
    }

    // Epilogue: c0,c1 -> (row, col..col+1); c2,c3 -> (row+8, ...)
    const int grp = lane >> 2, tig = lane & 3;
    #pragma unroll
    for (int mf = 0; mf < 4; mf++) {
        const int row = bm + wm + mf * 16 + grp;
        #pragma unroll
        for (int nf = 0; nf < 8; nf++) {
            const int col = bn + wn + nf * 8 + 2 * tig;
            *(float2*)(g_combined + (size_t)row * N_TOT + col) =
                make_float2(acc[mf][nf][0], acc[mf][nf][1]);
            *(float2*)(g_combined + (size_t)(row + 8) * N_TOT + col) =
                make_float2(acc[mf][nf][2], acc[mf][nf][3]);
        }
    }
}

// ---------------------------------------------------------------------------
// Kernel 2: per-(channel, chunk) max of c over its sequence chunk
// ---------------------------------------------------------------------------
__global__ void chunkmax_kernel() {
    const int idx = blockIdx.x * blockDim.x + threadIdx.x;
    if (idx >= NCH * NCHUNK) return;
    const int ch    = idx % NCH;
    const int chunk = idx / NCH;

    const int b    = ch / (HEADS * HD);
    const int rem  = ch % (HEADS * HD);
    const int head = rem / HD;
    const int hd   = rem % HD;

    const float* cptr = g_combined + (size_t)b * SEQ * N_TOT
                        + (size_t)2 * DIMX + (size_t)head * HD + hd;
    float m = -INFINITY;
    const int s0 = chunk * CLEN;
    for (int s = s0; s < s0 + CLEN; s++) {
        m = fmaxf(m, cptr[(size_t)s * N_TOT]);
    }
    g_chunkmax[(size_t)chunk * NCH + ch] = m;
}

// ---------------------------------------------------------------------------
// Kernel 3: carry-in, running cummax, fused combine, transposed store + state
// ---------------------------------------------------------------------------
__global__ void scan_out_kernel(const float* __restrict__ alphas,
                                float* __restrict__ out,
                                long long out_size) {
    const int idx = blockIdx.x * blockDim.x + threadIdx.x;
    if (idx >= NCH * NCHUNK) return;
    const int ch    = idx % NCH;
    const int chunk = idx / NCH;

    const int b    = ch / (HEADS * HD);
    const int rem  = ch % (HEADS * HD);
    const int head = rem / HD;
    const int hd   = rem % HD;

    const float a1 = alphas[0];
    const float a2 = alphas[1];
    const float a3 = alphas[2];

    float e = -INFINITY;
    for (int j = 0; j < chunk; j++)
        e = fmaxf(e, g_chunkmax[(size_t)j * NCH + ch]);

    const float* base = g_combined + (size_t)b * SEQ * N_TOT + (size_t)head * HD + hd;
    float* outp = out + (size_t)b * SEQ * DIMX + (size_t)hd * HEADS + head;

    const int s0 = chunk * CLEN;
    for (int s = s0; s < s0 + CLEN; s++) {
        const float* row = base + (size_t)s * N_TOT;
        const float av = row[0];
        const float bv = row[DIMX];
        const float cv = row[2 * DIMX];
        const float dv = row[3 * DIMX];
        e = fmaxf(e, cv);
        const float o = bv * (av + a1 + cv + e) + a2 * dv
                        + av * fmaf(a3, e, dv) + cv * e;
        outp[(size_t)s * DIMX] = o;
    }

    if (chunk == NCHUNK - 1) {
        const size_t state_base = (size_t)BATCH * SEQ * DIMX;
        if (out_size >= (long long)(state_base + (size_t)BATCH * HD * HEADS)) {
            out[state_base + (size_t)b * HD * HEADS + (size_t)hd * HEADS + head] = e;
        }
    }
}

// ---------------------------------------------------------------------------
extern "C" void kernel_launch(void* const* d_in, const int* in_sizes, int n_in,
                              void* d_out, int out_size) {
    const float* x      = (const float*)d_in[0];
    const float* W      = (const float*)d_in[1];
    const float* alphas = (const float*)d_in[2];
    float* out = (float*)d_out;

    cudaFuncSetAttribute(gemm_tf32_kernel,
                         cudaFuncAttributeMaxDynamicSharedMemorySize, SMEM_DYN);

    const size_t cvt_total = 2 * ((size_t)M_TOT * K_TOT / 4);
    cvt_kernel<<<(unsigned)((cvt_total + 255) / 256), 256>>>((const float4*)x, (const float4*)W);

    dim3 gemm_grid(N_TOT / BN, M_TOT / BM);   // (32, 64)
    gemm_tf32_kernel<<<gemm_grid, 256, SMEM_DYN>>>();

    const int scan_threads = NCH * NCHUNK;
    chunkmax_kernel<<<(scan_threads + 255) / 256, 256>>>();
    scan_out_kernel<<<(scan_threads + 255) / 256, 256>>>(alphas, out, (long long)out_size);
}

// round 10
// speedup vs baseline: 1.1395x; 1.1395x over previous
#include <cuda_runtime.h>
#include <math.h>
#include <stdint.h>

// Problem constants
#define DIMX   2048
#define HEADS  16
#define HD     128
#define BATCH  4
#define SEQ    2048
#define M_TOT  8192
#define N_TOT  8192
#define K_TOT  2048

// Scan chunking
#define NCHUNK 32
#define CLEN   (SEQ / NCHUNK)
#define NCH    (BATCH * HEADS * HD)

// Scratch
__device__ float g_combined[(size_t)M_TOT * N_TOT];
__device__ float g_chunkmax[(size_t)NCHUNK * NCH];
__device__ float g_Ar[(size_t)M_TOT * K_TOT];
__device__ float g_Br[(size_t)N_TOT * K_TOT];

// ---------------------------------------------------------------------------
// PTX helpers
// ---------------------------------------------------------------------------
__device__ __forceinline__ uint32_t smem_u32(const void* p) {
    uint32_t a;
    asm("{ .reg .u64 t; cvta.to.shared.u64 t, %1; cvt.u32.u64 %0, t; }" : "=r"(a) : "l"(p));
    return a;
}
__device__ __forceinline__ uint32_t f2tf32(float f) {
    uint32_t o; asm("cvt.rna.tf32.f32 %0, %1;" : "=r"(o) : "f"(f)); return o;
}
__device__ __forceinline__ void cp_async16(uint32_t dst, const void* src) {
    asm volatile("cp.async.cg.shared.global [%0], [%1], 16;\n" :: "r"(dst), "l"(src));
}
__device__ __forceinline__ void cp_commit() { asm volatile("cp.async.commit_group;\n"); }
template <int N> __device__ __forceinline__ void cp_wait() {
    asm volatile("cp.async.wait_group %0;\n" :: "n"(N));
}
__device__ __forceinline__ void ldmat_x4(uint32_t& r0, uint32_t& r1, uint32_t& r2, uint32_t& r3,
                                         uint32_t addr) {
    asm volatile("ldmatrix.sync.aligned.m8n8.x4.shared.b16 {%0,%1,%2,%3}, [%4];"
                 : "=r"(r0), "=r"(r1), "=r"(r2), "=r"(r3) : "r"(addr));
}
__device__ __forceinline__ void mma_tf32(float& c0, float& c1, float& c2, float& c3,
                                         uint32_t a0, uint32_t a1, uint32_t a2, uint32_t a3,
                                         uint32_t b0, uint32_t b1) {
    asm volatile(
        "mma.sync.aligned.m16n8k8.row.col.f32.tf32.tf32.f32 "
        "{%0,%1,%2,%3}, {%4,%5,%6,%7}, {%8,%9}, {%0,%1,%2,%3};\n"
        : "+f"(c0), "+f"(c1), "+f"(c2), "+f"(c3)
        : "r"(a0), "r"(a1), "r"(a2), "r"(a3), "r"(b0), "r"(b1));
}
#define SWZ128(off) ((off) ^ (((off) >> 3) & 0x70))

// ---------------------------------------------------------------------------
// Kernel 0: round x and W to tf32 (rna)
// ---------------------------------------------------------------------------
__global__ void cvt_kernel(const float4* __restrict__ x, const float4* __restrict__ w) {
    const size_t N4 = (size_t)M_TOT * K_TOT / 4;
    size_t i = (size_t)blockIdx.x * blockDim.x + threadIdx.x;
    float4* Ao = (float4*)g_Ar;
    float4* Bo = (float4*)g_Br;
    if (i < N4) {
        float4 v = x[i];
        float4 o;
        o.x = __uint_as_float(f2tf32(v.x));
        o.y = __uint_as_float(f2tf32(v.y));
        o.z = __uint_as_float(f2tf32(v.z));
        o.w = __uint_as_float(f2tf32(v.w));
        Ao[i] = o;
    } else if (i < 2 * N4) {
        size_t j = i - N4;
        float4 v = w[j];
        float4 o;
        o.x = __uint_as_float(f2tf32(v.x));
        o.y = __uint_as_float(f2tf32(v.y));
        o.z = __uint_as_float(f2tf32(v.z));
        o.w = __uint_as_float(f2tf32(v.w));
        Bo[j] = o;
    }
}

// ---------------------------------------------------------------------------
// Kernel 1: TF32 mma.sync GEMM, ldmatrix fragment loads, occupancy 2
// CTA tile 128x128, BK=32 (128B rows, SW128), 8 warps (2x4), warp tile 64x32
// 3-stage cp.async ring -> 96KB smem -> 2 CTAs/SM
// ---------------------------------------------------------------------------
#define BM 128
#define BN 128
#define BK 32
#define KT (K_TOT / BK)                        // 64
#define STAGES 3
#define A_STAGE_BYTES (BM * BK * 4)            // 16384
#define B_STAGE_BYTES (BN * BK * 4)            // 16384
#define STAGE_BYTES (A_STAGE_BYTES + B_STAGE_BYTES)
#define SMEM_DYN (STAGES * STAGE_BYTES + 1024) // 99328

__global__ __launch_bounds__(256, 2)
void gemm_tf32_kernel() {
    extern __shared__ char dynsmem[];

    const int tid  = threadIdx.x;
    const int warp = tid >> 5;
    const int lane = tid & 31;
    const int bm   = blockIdx.y * BM;
    const int bn   = blockIdx.x * BN;

    const uint32_t sbase = (smem_u32(dynsmem) + 1023u) & ~1023u;

    const int wm = (warp >> 2) * 64;   // warp m origin: 0 / 64
    const int wn = (warp & 3) * 32;    // warp n origin: 0..96

    // ldmatrix lane geometry (validated in R6: identical rel_err to LDS path)
    const int lr   = lane & 7;           // row within 8-row tile; swizzle XOR key
    const int gA1  = (lane >> 3) & 1;    // A: +8 rows
    const int gA2  = lane >> 4;          // A: +1 16B k-chunk
    const int gB1  = lane >> 4;          // B: +8 rows
    const int gB2  = (lane >> 3) & 1;    // B: +1 16B k-chunk

    uint32_t aRow[4], bRow[2];
    #pragma unroll
    for (int mf = 0; mf < 4; mf++)
        aRow[mf] = (uint32_t)(wm + mf * 16 + gA1 * 8 + lr) * 128u;
    #pragma unroll
    for (int nfp = 0; nfp < 2; nfp++)
        bRow[nfp] = (uint32_t)(wn + nfp * 16 + gB1 * 8 + lr) * 128u;

    // cp.async: A = 4 x 16B/thread/stage, B = 4 x 16B
    uint32_t swA[4], ofsA[4], swB[4], ofsB[4];
    #pragma unroll
    for (int i = 0; i < 4; i++) {
        int c = tid + i * 256;           // 0..1023
        int row = c >> 3, ch = c & 7;
        uint32_t sw = SWZ128((uint32_t)(row * 128 + ch * 16));
        swA[i]  = sw;
        ofsA[i] = (uint32_t)((bm + row) * K_TOT + ch * 4);
        swB[i]  = sw;
        ofsB[i] = (uint32_t)((bn + row) * K_TOT + ch * 4);
    }

    float acc[4][4][4];
    #pragma unroll
    for (int i = 0; i < 4; i++)
        #pragma unroll
        for (int j = 0; j < 4; j++)
            #pragma unroll
            for (int v = 0; v < 4; v++) acc[i][j][v] = 0.0f;

    auto load_stage = [&](int buf, int kt) {
        const uint32_t da = sbase + buf * STAGE_BYTES;
        const uint32_t db = da + A_STAGE_BYTES;
        const uint32_t ko = (uint32_t)(kt * BK);
        #pragma unroll
        for (int i = 0; i < 4; i++) cp_async16(da + swA[i], g_Ar + ofsA[i] + ko);
        #pragma unroll
        for (int i = 0; i < 4; i++) cp_async16(db + swB[i], g_Br + ofsB[i] + ko);
        cp_commit();
    };

    // Prologue: stages 0,1
    load_stage(0, 0);
    load_stage(1, 1);

    int buf = 0;
    #pragma unroll 1
    for (int kt = 0; kt < KT; kt++) {
        if (kt + 1 < KT) cp_wait<1>(); else cp_wait<0>();
        __syncthreads();

        // refill the buffer freed by iteration kt-1
        if (kt + 2 < KT) {
            int nb = buf + 2; if (nb >= STAGES) nb -= STAGES;
            load_stage(nb, kt + 2);
        }

        const uint32_t aOff = sbase + buf * STAGE_BYTES;
        const uint32_t bOff = aOff + A_STAGE_BYTES;

        #pragma unroll
        for (int ks = 0; ks < 4; ks++) {       // 4 x K=8 substeps
            const int kc = ks * 2;             // 16B-chunk index
            uint32_t a[4][4];
            #pragma unroll
            for (int mf = 0; mf < 4; mf++) {
                uint32_t addr = aOff + aRow[mf] + ((uint32_t)((kc + gA2) ^ lr) << 4);
                ldmat_x4(a[mf][0], a[mf][1], a[mf][2], a[mf][3], addr);
            }
            uint32_t b[2][4];
            #pragma unroll
            for (int nfp = 0; nfp < 2; nfp++) {
                uint32_t addr = bOff + bRow[nfp] + ((uint32_t)((kc + gB2) ^ lr) << 4);
                ldmat_x4(b[nfp][0], b[nfp][1], b[nfp][2], b[nfp][3], addr);
            }
            #pragma unroll
            for (int mf = 0; mf < 4; mf++)
                #pragma unroll
                for (int nfp = 0; nfp < 2; nfp++) {
                    mma_tf32(acc[mf][2 * nfp][0], acc[mf][2 * nfp][1],
                             acc[mf][2 * nfp][2], acc[mf][2 * nfp][3],
                             a[mf][0], a[mf][1], a[mf][2], a[mf][3],
                             b[nfp][0], b[nfp][1]);
                    mma_tf32(acc[mf][2 * nfp + 1][0], acc[mf][2 * nfp + 1][1],
                             acc[mf][2 * nfp + 1][2], acc[mf][2 * nfp + 1][3],
                             a[mf][0], a[mf][1], a[mf][2], a[mf][3],
                             b[nfp][2], b[nfp][3]);
                }
        }
        buf++; if (buf >= STAGES) buf = 0;
    }

    // Epilogue: c0,c1 -> (row, col..col+1); c2,c3 -> (row+8, ...)
    const int grp = lane >> 2, tig = lane & 3;
    #pragma unroll
    for (int mf = 0; mf < 4; mf++) {
        const int row = bm + wm + mf * 16 + grp;
        #pragma unroll
        for (int nf = 0; nf < 4; nf++) {
            const int col = bn + wn + nf * 8 + 2 * tig;
            *(float2*)(g_combined + (size_t)row * N_TOT + col) =
                make_float2(acc[mf][nf][0], acc[mf][nf][1]);
            *(float2*)(g_combined + (size_t)(row + 8) * N_TOT + col) =
                make_float2(acc[mf][nf][2], acc[mf][nf][3]);
        }
    }
}

// ---------------------------------------------------------------------------
// Kernel 2: per-(channel, chunk) max of c over its sequence chunk
// ---------------------------------------------------------------------------
__global__ void chunkmax_kernel() {
    const int idx = blockIdx.x * blockDim.x + threadIdx.x;
    if (idx >= NCH * NCHUNK) return;
    const int ch    = idx % NCH;
    const int chunk = idx / NCH;

    const int b    = ch / (HEADS * HD);
    const int rem  = ch % (HEADS * HD);
    const int head = rem / HD;
    const int hd   = rem % HD;

    const float* cptr = g_combined + (size_t)b * SEQ * N_TOT
                        + (size_t)2 * DIMX + (size_t)head * HD + hd;
    float m = -INFINITY;
    const int s0 = chunk * CLEN;
    for (int s = s0; s < s0 + CLEN; s++) {
        m = fmaxf(m, cptr[(size_t)s * N_TOT]);
    }
    g_chunkmax[(size_t)chunk * NCH + ch] = m;
}

// ---------------------------------------------------------------------------
// Kernel 3: carry-in, running cummax, fused combine, transposed store + state
// ---------------------------------------------------------------------------
__global__ void scan_out_kernel(const float* __restrict__ alphas,
                                float* __restrict__ out,
                                long long out_size) {
    const int idx = blockIdx.x * blockDim.x + threadIdx.x;
    if (idx >= NCH * NCHUNK) return;
    const int ch    = idx % NCH;
    const int chunk = idx / NCH;

    const int b    = ch / (HEADS * HD);
    const int rem  = ch % (HEADS * HD);
    const int head = rem / HD;
    const int hd   = rem % HD;

    const float a1 = alphas[0];
    const float a2 = alphas[1];
    const float a3 = alphas[2];

    float e = -INFINITY;
    for (int j = 0; j < chunk; j++)
        e = fmaxf(e, g_chunkmax[(size_t)j * NCH + ch]);

    const float* base = g_combined + (size_t)b * SEQ * N_TOT + (size_t)head * HD + hd;
    float* outp = out + (size_t)b * SEQ * DIMX + (size_t)hd * HEADS + head;

    const int s0 = chunk * CLEN;
    for (int s = s0; s < s0 + CLEN; s++) {
        const float* row = base + (size_t)s * N_TOT;
        const float av = row[0];
        const float bv = row[DIMX];
        const float cv = row[2 * DIMX];
        const float dv = row[3 * DIMX];
        e = fmaxf(e, cv);
        const float o = bv * (av + a1 + cv + e) + a2 * dv
                        + av * fmaf(a3, e, dv) + cv * e;
        outp[(size_t)s * DIMX] = o;
    }

    if (chunk == NCHUNK - 1) {
        const size_t state_base = (size_t)BATCH * SEQ * DIMX;
        if (out_size >= (long long)(state_base + (size_t)BATCH * HD * HEADS)) {
            out[state_base + (size_t)b * HD * HEADS + (size_t)hd * HEADS + head] = e;
        }
    }
}

// ---------------------------------------------------------------------------
extern "C" void kernel_launch(void* const* d_in, const int* in_sizes, int n_in,
                              void* d_out, int out_size) {
    const float* x      = (const float*)d_in[0];
    const float* W      = (const float*)d_in[1];
    const float* alphas = (const float*)d_in[2];
    float* out = (float*)d_out;

    cudaFuncSetAttribute(gemm_tf32_kernel,
                         cudaFuncAttributeMaxDynamicSharedMemorySize, SMEM_DYN);

    const size_t cvt_total = 2 * ((size_t)M_TOT * K_TOT / 4);
    cvt_kernel<<<(unsigned)((cvt_total + 255) / 256), 256>>>((const float4*)x, (const float4*)W);

    dim3 gemm_grid(N_TOT / BN, M_TOT / BM);   // (64, 64)
    gemm_tf32_kernel<<<gemm_grid, 256, SMEM_DYN>>>();

    const int scan_threads = NCH * NCHUNK;
    chunkmax_kernel<<<(scan_threads + 255) / 256, 256>>>();
    scan_out_kernel<<<(scan_threads + 255) / 256, 256>>>(alphas, out, (long long)out_size);
}

// round 11
// speedup vs baseline: 3.1104x; 2.7295x over previous
#include <cuda_runtime.h>
#include <cuda_fp16.h>
#include <math.h>
#include <stdint.h>

// Problem constants
#define DIMX   2048
#define HEADS  16
#define HD     128
#define BATCH  4
#define SEQ    2048
#define M_TOT  8192
#define N_TOT  8192
#define K_TOT  2048

// Scan chunking
#define NCHUNK 32
#define CLEN   (SEQ / NCHUNK)
#define NCH    (BATCH * HEADS * HD)

// Scratch
__device__ float  g_combined[(size_t)M_TOT * N_TOT];   // 256 MB
__device__ float  g_chunkmax[(size_t)NCHUNK * NCH];
__device__ __half g_Ah[(size_t)M_TOT * K_TOT];         // 32 MB
__device__ __half g_Bh[(size_t)N_TOT * K_TOT];         // 32 MB

// ---------------------------------------------------------------------------
// PTX helpers
// ---------------------------------------------------------------------------
__device__ __forceinline__ uint32_t smem_u32(const void* p) {
    uint32_t a;
    asm("{ .reg .u64 t; cvta.to.shared.u64 t, %1; cvt.u32.u64 %0, t; }" : "=r"(a) : "l"(p));
    return a;
}
__device__ __forceinline__ void cp_async16(uint32_t dst, const void* src) {
    asm volatile("cp.async.cg.shared.global [%0], [%1], 16;\n" :: "r"(dst), "l"(src));
}
__device__ __forceinline__ void cp_commit() { asm volatile("cp.async.commit_group;\n"); }
template <int N> __device__ __forceinline__ void cp_wait() {
    asm volatile("cp.async.wait_group %0;\n" :: "n"(N));
}
__device__ __forceinline__ void ldmat_x4(uint32_t& r0, uint32_t& r1, uint32_t& r2, uint32_t& r3,
                                         uint32_t addr) {
    asm volatile("ldmatrix.sync.aligned.m8n8.x4.shared.b16 {%0,%1,%2,%3}, [%4];"
                 : "=r"(r0), "=r"(r1), "=r"(r2), "=r"(r3) : "r"(addr));
}
// m16n8k16 fp16 MMA, fp32 accumulate
__device__ __forceinline__ void mma_f16(float& c0, float& c1, float& c2, float& c3,
                                        uint32_t a0, uint32_t a1, uint32_t a2, uint32_t a3,
                                        uint32_t b0, uint32_t b1) {
    asm volatile(
        "mma.sync.aligned.m16n8k16.row.col.f32.f16.f16.f32 "
        "{%0,%1,%2,%3}, {%4,%5,%6,%7}, {%8,%9}, {%0,%1,%2,%3};\n"
        : "+f"(c0), "+f"(c1), "+f"(c2), "+f"(c3)
        : "r"(a0), "r"(a1), "r"(a2), "r"(a3), "r"(b0), "r"(b1));
}
#define SWZ128(off) ((off) ^ (((off) >> 3) & 0x70))

// ---------------------------------------------------------------------------
// Kernel 0: convert x and W to fp16 (rn)
// ---------------------------------------------------------------------------
__global__ void cvt_kernel(const float4* __restrict__ x, const float4* __restrict__ w) {
    const size_t N8 = (size_t)M_TOT * K_TOT / 8;   // 8 floats -> 8 halves per thread
    size_t i = (size_t)blockIdx.x * blockDim.x + threadIdx.x;
    if (i < N8) {
        float4 v0 = x[2 * i], v1 = x[2 * i + 1];
        __half2* o = (__half2*)(g_Ah + 8 * i);
        o[0] = __floats2half2_rn(v0.x, v0.y);
        o[1] = __floats2half2_rn(v0.z, v0.w);
        o[2] = __floats2half2_rn(v1.x, v1.y);
        o[3] = __floats2half2_rn(v1.z, v1.w);
    } else if (i < 2 * N8) {
        size_t j = i - N8;
        float4 v0 = w[2 * j], v1 = w[2 * j + 1];
        __half2* o = (__half2*)(g_Bh + 8 * j);
        o[0] = __floats2half2_rn(v0.x, v0.y);
        o[1] = __floats2half2_rn(v0.z, v0.w);
        o[2] = __floats2half2_rn(v1.x, v1.y);
        o[3] = __floats2half2_rn(v1.z, v1.w);
    }
}

// ---------------------------------------------------------------------------
// Kernel 1: FP16 mma.sync m16n8k16 GEMM, ldmatrix, occupancy 2
// CTA tile 128x128, BK=64 halves (128B rows, SW128), 8 warps, warp tile 64x32
// 3-stage cp.async ring -> 96KB smem -> 2 CTAs/SM
// ---------------------------------------------------------------------------
#define BM 128
#define BN 128
#define BK 64
#define KT (K_TOT / BK)                        // 32
#define STAGES 3
#define A_STAGE_BYTES (BM * BK * 2)            // 16384
#define B_STAGE_BYTES (BN * BK * 2)            // 16384
#define STAGE_BYTES (A_STAGE_BYTES + B_STAGE_BYTES)
#define SMEM_DYN (STAGES * STAGE_BYTES + 1024) // 99328

__global__ __launch_bounds__(256, 2)
void gemm_f16_kernel() {
    extern __shared__ char dynsmem[];

    const int tid  = threadIdx.x;
    const int warp = tid >> 5;
    const int lane = tid & 31;
    const int bm   = blockIdx.y * BM;
    const int bn   = blockIdx.x * BN;

    const uint32_t sbase = (smem_u32(dynsmem) + 1023u) & ~1023u;

    const int wm = (warp >> 2) * 64;   // warp m origin
    const int wn = (warp & 3) * 32;    // warp n origin

    // ldmatrix lane geometry (m16n8k16 fragments; same map as validated tf32 path)
    const int lr   = lane & 7;           // row within 8-row tile; swizzle XOR key
    const int gA1  = (lane >> 3) & 1;    // A: +8 rows     (matrices 1,3)
    const int gA2  = lane >> 4;          // A: +1 16B chunk (matrices 2,3)
    const int gB1  = lane >> 4;          // B: +8 n-rows   (matrices 2,3)
    const int gB2  = (lane >> 3) & 1;    // B: +1 16B chunk (matrices 1,3)

    uint32_t aRow[4], bRow[2];
    #pragma unroll
    for (int mf = 0; mf < 4; mf++)
        aRow[mf] = (uint32_t)(wm + mf * 16 + gA1 * 8 + lr) * 128u;
    #pragma unroll
    for (int nfp = 0; nfp < 2; nfp++)
        bRow[nfp] = (uint32_t)(wn + nfp * 16 + gB1 * 8 + lr) * 128u;

    // cp.async: tile = 128 rows x 8 chunks(16B) = 1024 slots; 4 per thread, A and B
    uint32_t swS[4], ofsA[4], ofsB[4];
    #pragma unroll
    for (int i = 0; i < 4; i++) {
        int c = tid + i * 256;           // 0..1023
        int row = c >> 3, ch = c & 7;
        swS[i]  = SWZ128((uint32_t)(row * 128 + ch * 16));
        ofsA[i] = (uint32_t)((bm + row) * K_TOT + ch * 8);   // half elements
        ofsB[i] = (uint32_t)((bn + row) * K_TOT + ch * 8);
    }

    float acc[4][4][4];
    #pragma unroll
    for (int i = 0; i < 4; i++)
        #pragma unroll
        for (int j = 0; j < 4; j++)
            #pragma unroll
            for (int v = 0; v < 4; v++) acc[i][j][v] = 0.0f;

    auto load_stage = [&](int buf, int kt) {
        const uint32_t da = sbase + buf * STAGE_BYTES;
        const uint32_t db = da + A_STAGE_BYTES;
        const uint32_t ko = (uint32_t)(kt * BK);
        #pragma unroll
        for (int i = 0; i < 4; i++) cp_async16(da + swS[i], g_Ah + ofsA[i] + ko);
        #pragma unroll
        for (int i = 0; i < 4; i++) cp_async16(db + swS[i], g_Bh + ofsB[i] + ko);
        cp_commit();
    };

    load_stage(0, 0);
    load_stage(1, 1);

    int buf = 0;
    #pragma unroll 1
    for (int kt = 0; kt < KT; kt++) {
        if (kt + 1 < KT) cp_wait<1>(); else cp_wait<0>();
        __syncthreads();

        if (kt + 2 < KT) {
            int nb = buf + 2; if (nb >= STAGES) nb -= STAGES;
            load_stage(nb, kt + 2);
        }

        const uint32_t aOff = sbase + buf * STAGE_BYTES;
        const uint32_t bOff = aOff + A_STAGE_BYTES;

        #pragma unroll
        for (int ks = 0; ks < 4; ks++) {       // 4 x K=16 substeps (BK=64)
            const int kc = ks * 2;             // 16B-chunk base of this k16
            uint32_t a[4][4];
            #pragma unroll
            for (int mf = 0; mf < 4; mf++) {
                uint32_t addr = aOff + aRow[mf] + ((uint32_t)((kc + gA2) ^ lr) << 4);
                ldmat_x4(a[mf][0], a[mf][1], a[mf][2], a[mf][3], addr);
            }
            uint32_t b[2][4];
            #pragma unroll
            for (int nfp = 0; nfp < 2; nfp++) {
                uint32_t addr = bOff + bRow[nfp] + ((uint32_t)((kc + gB2) ^ lr) << 4);
                ldmat_x4(b[nfp][0], b[nfp][1], b[nfp][2], b[nfp][3], addr);
            }
            #pragma unroll
            for (int mf = 0; mf < 4; mf++)
                #pragma unroll
                for (int nfp = 0; nfp < 2; nfp++) {
                    mma_f16(acc[mf][2 * nfp][0], acc[mf][2 * nfp][1],
                            acc[mf][2 * nfp][2], acc[mf][2 * nfp][3],
                            a[mf][0], a[mf][1], a[mf][2], a[mf][3],
                            b[nfp][0], b[nfp][1]);
                    mma_f16(acc[mf][2 * nfp + 1][0], acc[mf][2 * nfp + 1][1],
                            acc[mf][2 * nfp + 1][2], acc[mf][2 * nfp + 1][3],
                            a[mf][0], a[mf][1], a[mf][2], a[mf][3],
                            b[nfp][2], b[nfp][3]);
                }
        }
        buf++; if (buf >= STAGES) buf = 0;
    }

    // Epilogue: c0,c1 -> (row, col..col+1); c2,c3 -> (row+8, ...)
    const int grp = lane >> 2, tig = lane & 3;
    #pragma unroll
    for (int mf = 0; mf < 4; mf++) {
        const int row = bm + wm + mf * 16 + grp;
        #pragma unroll
        for (int nf = 0; nf < 4; nf++) {
            const int col = bn + wn + nf * 8 + 2 * tig;
            *(float2*)(g_combined + (size_t)row * N_TOT + col) =
                make_float2(acc[mf][nf][0], acc[mf][nf][1]);
            *(float2*)(g_combined + (size_t)(row + 8) * N_TOT + col) =
                make_float2(acc[mf][nf][2], acc[mf][nf][3]);
        }
    }
}

// ---------------------------------------------------------------------------
// Kernel 2: per-(channel, chunk) max of c over its sequence chunk
// ---------------------------------------------------------------------------
__global__ void chunkmax_kernel() {
    const int idx = blockIdx.x * blockDim.x + threadIdx.x;
    if (idx >= NCH * NCHUNK) return;
    const int ch    = idx % NCH;
    const int chunk = idx / NCH;

    const int b    = ch / (HEADS * HD);
    const int rem  = ch % (HEADS * HD);
    const int head = rem / HD;
    const int hd   = rem % HD;

    const float* cptr = g_combined + (size_t)b * SEQ * N_TOT
                        + (size_t)2 * DIMX + (size_t)head * HD + hd;
    float m = -INFINITY;
    const int s0 = chunk * CLEN;
    for (int s = s0; s < s0 + CLEN; s++) {
        m = fmaxf(m, cptr[(size_t)s * N_TOT]);
    }
    g_chunkmax[(size_t)chunk * NCH + ch] = m;
}

// ---------------------------------------------------------------------------
// Kernel 3: carry-in, running cummax, fused combine, transposed store + state
// ---------------------------------------------------------------------------
__global__ void scan_out_kernel(const float* __restrict__ alphas,
                                float* __restrict__ out,
                                long long out_size) {
    const int idx = blockIdx.x * blockDim.x + threadIdx.x;
    if (idx >= NCH * NCHUNK) return;
    const int ch    = idx % NCH;
    const int chunk = idx / NCH;

    const int b    = ch / (HEADS * HD);
    const int rem  = ch % (HEADS * HD);
    const int head = rem / HD;
    const int hd   = rem % HD;

    const float a1 = alphas[0];
    const float a2 = alphas[1];
    const float a3 = alphas[2];

    float e = -INFINITY;
    for (int j = 0; j < chunk; j++)
        e = fmaxf(e, g_chunkmax[(size_t)j * NCH + ch]);

    const float* base = g_combined + (size_t)b * SEQ * N_TOT + (size_t)head * HD + hd;
    float* outp = out + (size_t)b * SEQ * DIMX + (size_t)hd * HEADS + head;

    const int s0 = chunk * CLEN;
    for (int s = s0; s < s0 + CLEN; s++) {
        const float* row = base + (size_t)s * N_TOT;
        const float av = row[0];
        const float bv = row[DIMX];
        const float cv = row[2 * DIMX];
        const float dv = row[3 * DIMX];
        e = fmaxf(e, cv);
        const float o = bv * (av + a1 + cv + e) + a2 * dv
                        + av * fmaf(a3, e, dv) + cv * e;
        outp[(size_t)s * DIMX] = o;
    }

    if (chunk == NCHUNK - 1) {
        const size_t state_base = (size_t)BATCH * SEQ * DIMX;
        if (out_size >= (long long)(state_base + (size_t)BATCH * HD * HEADS)) {
            out[state_base + (size_t)b * HD * HEADS + (size_t)hd * HEADS + head] = e;
        }
    }
}

// ---------------------------------------------------------------------------
extern "C" void kernel_launch(void* const* d_in, const int* in_sizes, int n_in,
                              void* d_out, int out_size) {
    const float* x      = (const float*)d_in[0];
    const float* W      = (const float*)d_in[1];
    const float* alphas = (const float*)d_in[2];
    float* out = (float*)d_out;

    cudaFuncSetAttribute(gemm_f16_kernel,
                         cudaFuncAttributeMaxDynamicSharedMemorySize, SMEM_DYN);

    const size_t cvt_total = 2 * ((size_t)M_TOT * K_TOT / 8);
    cvt_kernel<<<(unsigned)((cvt_total + 255) / 256), 256>>>((const float4*)x, (const float4*)W);

    dim3 gemm_grid(N_TOT / BN, M_TOT / BM);   // (64, 64)
    gemm_f16_kernel<<<gemm_grid, 256, SMEM_DYN>>>();

    const int scan_threads = NCH * NCHUNK;
    chunkmax_kernel<<<(scan_threads + 255) / 256, 256>>>();
    scan_out_kernel<<<(scan_threads + 255) / 256, 256>>>(alphas, out, (long long)out_size);
}